// round 1
// baseline (speedup 1.0000x reference)
#include <cuda_runtime.h>
#include <cstdint>
#include <math.h>

#define FULL_MASK 0xFFFFFFFFu

constexpr int N_COLS = 32768;
constexpr int TPB    = 1024;
constexpr int VPT    = 32;    // values per thread (N_COLS / TPB)
constexpr int KTOP   = 64;
constexpr int NT     = 10;    // threshold count
constexpr int CAP    = 2048;  // candidate buffer capacity

// Order-preserving float->uint key (larger float => larger key)
__device__ __forceinline__ unsigned f2k(float f) {
    unsigned u = __float_as_uint(f);
    return (u & 0x80000000u) ? ~u : (u | 0x80000000u);
}
__device__ __forceinline__ float k2f(unsigned k) {
    unsigned u = (k & 0x80000000u) ? (k & 0x7FFFFFFFu) : ~k;
    return __uint_as_float(u);
}

__global__ __launch_bounds__(TPB, 1)
void remaxkv_kernel(const float* __restrict__ x, float* __restrict__ out) {
    const int row  = blockIdx.x;
    const int tid  = threadIdx.x;
    const int lane = tid & 31;
    const int warp = tid >> 5;

    const float4* xr   = reinterpret_cast<const float4*>(x + (size_t)row * N_COLS);
    float4*       outr = reinterpret_cast<float4*>(out + (size_t)row * N_COLS);

    __shared__ float    s_msum[32];
    __shared__ int      s_cnt[NT][32];
    __shared__ unsigned s_candk[CAP];
    __shared__ int      s_ncand;
    __shared__ float    s_mag;
    __shared__ float    s_ratio;
    __shared__ float    s_tlo;
    __shared__ unsigned s_klo, s_khi;
    __shared__ int      s_flags;
    __shared__ int      s_tot;

    // ---- Load entire row into registers (coalesced float4, streaming) ----
    float xv[VPT];
#pragma unroll
    for (int i = 0; i < 8; i++) {
        float4 t = __ldcs(xr + i * TPB + tid);
        xv[4*i+0] = t.x; xv[4*i+1] = t.y; xv[4*i+2] = t.z; xv[4*i+3] = t.w;
    }

    // ---- relu-sum + multi-threshold counts (pure ALU, overlaps load latency) ----
    const float TH[NT] = {3.6f, 3.2f, 3.0f, 2.9f, 2.8f, 2.7f, 2.6f, 2.45f, 2.2f, 2.0f};
    float ms = 0.f;
    int cnt[NT];
#pragma unroll
    for (int t = 0; t < NT; t++) cnt[t] = 0;
#pragma unroll
    for (int j = 0; j < VPT; j++) {
        float v = xv[j];
        ms += fmaxf(v, 0.f);
#pragma unroll
        for (int t = 0; t < NT; t++) cnt[t] += (v >= TH[t]) ? 1 : 0;
    }

    // ---- deterministic block reduce: warp shfl/REDUX -> smem -> warp 0 ----
#pragma unroll
    for (int o = 16; o; o >>= 1) ms += __shfl_xor_sync(FULL_MASK, ms, o);
#pragma unroll
    for (int t = 0; t < NT; t++) cnt[t] = __reduce_add_sync(FULL_MASK, cnt[t]);
    if (lane == 0) {
        s_msum[warp] = ms;
#pragma unroll
        for (int t = 0; t < NT; t++) s_cnt[t][warp] = cnt[t];
    }
    if (tid == 0) s_ncand = 0;
    __syncthreads();

    if (warp == 0) {
        float m = s_msum[lane];
#pragma unroll
        for (int o = 16; o; o >>= 1) m += __shfl_xor_sync(FULL_MASK, m, o);
        int c[NT];
#pragma unroll
        for (int t = 0; t < NT; t++) {
            c[t] = s_cnt[t][lane];
            c[t] = __reduce_add_sync(FULL_MASK, c[t]);
        }
        if (lane == 0) {
            s_mag = m;
            int sel = -1;
#pragma unroll
            for (int t = 0; t < NT; t++) {
                if (sel < 0 && c[t] >= KTOP) sel = t;
            }
            if (sel < 0) {
                s_flags = 1;                 // fallback: 64th value below lowest threshold
            } else {
                s_flags = 0;
                s_tlo = TH[sel];
                s_klo = f2k(TH[sel]);
                // hi key: next-higher threshold (count < K), or +inf key for sel==0
                s_khi = (sel > 0) ? f2k(TH[sel - 1]) : 0xFF800000u;
            }
        }
    }
    __syncthreads();

    int fb = s_flags;

    // ---- fast path: warp-aggregated compaction of candidates >= t_lo ----
    if (!fb) {
        float tlo = s_tlo;
#pragma unroll
        for (int j = 0; j < VPT; j++) {
            bool p = (xv[j] >= tlo);
            unsigned m = __ballot_sync(FULL_MASK, p);
            if (m) {
                int nset   = __popc(m);
                int leader = __ffs(m) - 1;
                int base   = 0;
                if (lane == leader) base = atomicAdd(&s_ncand, nset);
                base = __shfl_sync(FULL_MASK, base, leader);
                if (p) {
                    int slot = base + __popc(m & ((1u << lane) - 1u));
                    if (slot < CAP) s_candk[slot] = f2k(xv[j]);
                }
            }
        }
        __syncthreads();
        if (s_ncand > CAP) fb = 1;   // overflow -> generic path (uniform decision)
    }

    if (!fb) {
        // ---- single-warp exact bisection for the K-th largest key ----
        if (warp == 0) {
            int nc = s_ncand;
            unsigned lo = s_klo, hi = s_khi;
            while (hi - lo > 1u) {
                unsigned mid = lo + ((hi - lo) >> 1);
                int c = 0;
                for (int j = lane; j < nc; j += 32) c += (s_candk[j] >= mid) ? 1 : 0;
                c = __reduce_add_sync(FULL_MASK, c);
                if (c >= KTOP) lo = mid; else hi = mid;
            }
            // exact top-K sum with tie correction at key == lo
            float s = 0.f; int cg = 0;
            for (int j = lane; j < nc; j += 32) {
                unsigned k = s_candk[j];
                if (k > lo) { s += k2f(k); cg++; }
            }
#pragma unroll
            for (int o = 16; o; o >>= 1) s += __shfl_xor_sync(FULL_MASK, s, o);
            cg = __reduce_add_sync(FULL_MASK, cg);
            if (lane == 0) {
                float magk = s + (float)(KTOP - cg) * k2f(lo);
                float r = magk / s_mag;
                if (!isfinite(r)) r = 0.f;
                s_ratio = r;
            }
        }
    } else {
        // ---- generic fallback: block-wide bisection over full key range ----
        unsigned lo = 0u, hi = 0xFFFFFFFFu;
        for (int it = 0; it < 33 && (hi - lo) > 1u; it++) {
            unsigned mid = lo + ((hi - lo) >> 1);
            int c = 0;
#pragma unroll
            for (int j = 0; j < VPT; j++) c += (f2k(xv[j]) >= mid) ? 1 : 0;
            c = __reduce_add_sync(FULL_MASK, c);
            if (lane == 0) s_cnt[0][warp] = c;
            __syncthreads();
            if (warp == 0) {
                int cc = s_cnt[0][lane];
                cc = __reduce_add_sync(FULL_MASK, cc);
                if (lane == 0) s_tot = cc;
            }
            __syncthreads();
            int ct = s_tot;
            if (ct >= KTOP) lo = mid; else hi = mid;
        }
        float s = 0.f; int cg = 0;
#pragma unroll
        for (int j = 0; j < VPT; j++) {
            unsigned k = f2k(xv[j]);
            if (k > lo) { s += xv[j]; cg++; }
        }
#pragma unroll
        for (int o = 16; o; o >>= 1) s += __shfl_xor_sync(FULL_MASK, s, o);
        cg = __reduce_add_sync(FULL_MASK, cg);
        if (lane == 0) { s_msum[warp] = s; s_cnt[0][warp] = cg; }
        __syncthreads();
        if (warp == 0) {
            float ss = s_msum[lane];
#pragma unroll
            for (int o = 16; o; o >>= 1) ss += __shfl_xor_sync(FULL_MASK, ss, o);
            int cc = s_cnt[0][lane];
            cc = __reduce_add_sync(FULL_MASK, cc);
            if (lane == 0) {
                float magk = ss + (float)(KTOP - cc) * k2f(lo);
                float r = magk / s_mag;
                if (!isfinite(r)) r = 0.f;
                s_ratio = r;
            }
        }
    }
    __syncthreads();

    // ---- scaled relu write-out from registers (streaming stores) ----
    float r = s_ratio;
#pragma unroll
    for (int i = 0; i < 8; i++) {
        float4 o;
        o.x = fmaxf(xv[4*i+0], 0.f) * r;
        o.y = fmaxf(xv[4*i+1], 0.f) * r;
        o.z = fmaxf(xv[4*i+2], 0.f) * r;
        o.w = fmaxf(xv[4*i+3], 0.f) * r;
        __stcs(outr + i * TPB + tid, o);
    }
}

extern "C" void kernel_launch(void* const* d_in, const int* in_sizes, int n_in,
                              void* d_out, int out_size) {
    const float* x  = (const float*)d_in[0];
    float*      out = (float*)d_out;
    int n    = in_sizes[0];
    int rows = n / N_COLS;
    remaxkv_kernel<<<rows, TPB>>>(x, out);
}